// round 17
// baseline (speedup 1.0000x reference)
#include <cuda_runtime.h>
#include <cstdint>

// Focal CTC loss — bidirectional split scan, EIGHT timesteps per barrier.
// R16 linear float4 pair state (vU,vV,exp) + 8-step redundant linear pyramid
// (9 neighbor pairs), emissions ex2'd in-body from a 32-deep raw cp.async ring.
// grid = 2B (dir = bid&1, b = bid>>1), block = 160 (warps 0-3 compute pair
// j = tid, warp 4 = ring). Fixed barrier/LDS/issue overhead now amortized
// over 8 steps. Second finisher per sample combines ll = LSE_s(aTm + bTm) and
// focal weights; final scalar factorizes: mean(loss)*mean(w).

#define CFIX  256
#define DEPTH 32
#define KS    8
#define NEG2  (-1e30f)
#define DEADE (-1e9f)
#define LOG2E 1.4426950408889634f
#define LN2   0.6931471805599453f

__device__ float    g_mid[64][2][128][2];
__device__ float    g_tps[64][2][128];
__device__ unsigned g_done[64];
__device__ float    g_loss[64];
__device__ float    g_wsum[64];
__device__ unsigned g_ctr = 0;

__device__ __forceinline__ float ex2f(float x){ float y; asm("ex2.approx.ftz.f32 %0,%1;":"=f"(y):"f"(x)); return y; }
__device__ __forceinline__ float lg2f(float x){ float y; asm("lg2.approx.ftz.f32 %0,%1;":"=f"(y):"f"(x)); return y; }

__device__ __forceinline__ float lse2p(float a, float b, float e) {
    float hi = fmaxf(a, b), lo = fminf(a, b);
    return fmaf(e, LOG2E, hi + lg2f(1.0f + ex2f(lo - hi)));
}
__device__ __forceinline__ float lse3p(float a, float b, float c, float e) {
    float hi = fmaxf(a, b), lo = fminf(a, b);
    float m  = fmaxf(hi, c), o1 = fminf(hi, c);
    return fmaf(e, LOG2E, m + lg2f(1.0f + ex2f(o1 - m) + ex2f(lo - m)));
}
__device__ __forceinline__ float lse2(float a, float b) {
    float hi = fmaxf(a, b), lo = fminf(a, b);
    return hi + lg2f(1.0f + ex2f(lo - hi));
}
__device__ __forceinline__ float lse3(float a, float b, float c) {
    float hi = fmaxf(a, b), lo = fminf(a, b);
    float m  = fmaxf(hi, c), o1 = fminf(hi, c);
    return m + lg2f(1.0f + ex2f(o1 - m) + ex2f(lo - m));
}
__device__ __forceinline__ float toLog(float v, float e) {
    return (v > 0.0f) ? (lg2f(v) + e) : NEG2;
}

__device__ __forceinline__ void finalize(float* out, int B, int L)
{
    __threadfence();
    unsigned v = atomicAdd(&g_ctr, 1u);
    if (v == (unsigned)(B - 1)) {
        g_ctr = 0;
        __threadfence();
        float ls = 0.0f, ws = 0.0f;
        for (int i = 0; i < B; i++) {
            ls += __ldcg(&g_loss[i]);
            ws += __ldcg(&g_wsum[i]);
        }
        out[0] = (ls / (float)B) * (ws / ((float)B * (float)L));
    }
}

__global__ __launch_bounds__(160, 1)
void focal_ctc_kernel(const float* __restrict__ lp,      // (T,B,C)
                      const int*   __restrict__ targets, // (B*L)
                      const int*   __restrict__ in_len,  // (B)
                      const int*   __restrict__ tg_len,  // (B)
                      float*       __restrict__ out,
                      int T, int B, int L)
{
    __shared__ __align__(16) float  ring[DEPTH][CFIX];  // raw rows (32 KB)
    __shared__ __align__(16) float4 ab4[2][136];        // pair state (vU,vV,e,_)
    __shared__ float redm[4], reds[4], redww[4];
    __shared__ unsigned sflag;

    const int tid = threadIdx.x, w = tid >> 5, lane = tid & 31;
    const int bid = blockIdx.x;
    const int dir = bid & 1, b = bid >> 1;
    const int len = in_len[b], tl = tg_len[b];
    const int bL  = b * L;
    const int Tm  = len >> 1;
    const int nB  = len - 1 - Tm;
    const size_t tstr = (size_t)B * CFIX;
    const float* rowb = lp + (size_t)b * CFIX;

    uint32_t ringA = (uint32_t)__cvta_generic_to_shared(&ring[0][0]);
    #define ISSUE(SLOT, ROW)                                                        \
    {                                                                               \
        const float* s0_ = rowb + (size_t)(ROW) * tstr + lane * 4;                  \
        uint32_t d0_ = ringA + (uint32_t)(SLOT) * (CFIX * 4) + lane * 16;           \
        asm volatile("cp.async.ca.shared.global [%0], [%1], 16;" :: "r"(d0_),       "l"(s0_) : "memory"); \
        asm volatile("cp.async.ca.shared.global [%0], [%1], 16;" :: "r"(d0_ + 512), "l"(s0_ + 128) : "memory"); \
    }

    // pads: fwd layout pair at [8+j] (pads 0..7); bwd layout pair at [j] (pads 128..135)
    if (tid < 8)  { ab4[0][tid] = make_float4(0,0,DEADE,0); ab4[1][tid] = make_float4(0,0,DEADE,0); }
    if (tid >= 128 && tid < 136) { ab4[0][tid] = make_float4(0,0,DEADE,0); ab4[1][tid] = make_float4(0,0,DEADE,0); }

    const int j = tid;                 // pair index (compute warps)
    const bool cw = (w < 4);
    const bool hasU = cw && (j <= L);
    const bool hasV = cw && (j <= L - 1);

    float vU = 0.f, vV = 0.f, eS = DEADE, acc = 0.0f;

    if (dir == 0) {
        // ======================= FORWARD =======================
        int   c[KS + 1];
        float af[KS];
        if (cw) {
            #pragma unroll
            for (int p = 0; p <= KS; p++) {
                int idx = j - p;
                c[p] = (idx >= 0 && idx < L) ? targets[bL + idx] : 0;
            }
            #pragma unroll
            for (int p = 0; p < KS; p++) {
                int idx = j - p;
                af[p] = (idx >= 1 && idx < L && c[p] != c[p + 1]) ? 1.f : 0.f;
            }
        }
        const int nI = (Tm >= KS) ? ((Tm - KS) >> 3) + 1 : 0;  // intervals t = 1+8i, t+7 <= Tm

        if (w == 4) {                  // prologue: rows 0..23 committed, 0..8 complete
            #pragma unroll
            for (int i = 0; i < 24; i++) {
                if (i <= Tm) ISSUE(i & 31, i)
                asm volatile("cp.async.commit_group;" ::: "memory");
            }
            asm volatile("cp.async.wait_group 15;" ::: "memory");
        }
        __syncthreads();

        // t = 0 init
        if (cw) {
            float lc = ring[0][c[0]];
            acc = ex2f(lc * LOG2E);
            if (j == 0) {
                float xU = ring[0][0] * LOG2E;
                float xV = lc * LOG2E;
                eS = floorf(fmaxf(xU, xV));
                vU = ex2f(xU - eS);
                vV = ex2f(xV - eS);
            }
            ab4[0][8 + j] = make_float4(vU, vV, eS, 0);
        }

        int rb = 0;
        for (int i = 0; i < nI; i++) {
            __syncthreads();
            const int t = 1 + KS * i;
            if (w == 4) {
                #pragma unroll
                for (int q = 0; q < 8; q++) {
                    int r = 24 + 8 * i + q;
                    if (r <= Tm) ISSUE(r & 31, r)
                    asm volatile("cp.async.commit_group;" ::: "memory");
                }
                asm volatile("cp.async.wait_group 15;" ::: "memory");
            } else if (cw) {
                float U[KS + 1], V[KS + 1];
                float me = eS;
                float4 nb[KS];
                #pragma unroll
                for (int p = 0; p < KS; p++) {
                    nb[p] = ab4[rb][8 + j - 1 - p];
                    me = fmaxf(me, nb[p].z);
                }
                {
                    float s0 = ex2f(eS - me);
                    U[0] = vU * s0; V[0] = vV * s0;
                }
                #pragma unroll
                for (int p = 0; p < KS; p++) {
                    float s = ex2f(nb[p].z - me);
                    U[p + 1] = nb[p].x * s;
                    V[p + 1] = nb[p].y * s;
                }
                // 8-step pyramid
                #pragma unroll
                for (int s = 0; s < KS; s++) {
                    const float* R = &ring[(t + s) & 31][0];
                    float pB = ex2f(R[0] * LOG2E);
                    float pa0 = ex2f(R[c[0]] * LOG2E);
                    acc += pa0;
                    #pragma unroll
                    for (int p = 0; p < KS - s; p++) {
                        float pA = (p == 0) ? pa0 : ex2f(R[c[p]] * LOG2E);
                        float nU = (U[p] + V[p + 1]) * pB;
                        float nV = fmaf(af[p], V[p + 1], V[p] + U[p]) * pA;
                        U[p] = nU; V[p] = nV;
                    }
                }
                float qU = hasU ? U[0] : 0.f;
                float qV = hasV ? V[0] : 0.f;
                float mm = fmaxf(qU, qV);
                if (mm > 0.f) {
                    int ex = (int)(__float_as_uint(mm) >> 23) - 127;
                    float scl = __uint_as_float((unsigned)(127 - ex) << 23);
                    vU = qU * scl; vV = qV * scl; eS = me + (float)ex;
                } else { vU = 0.f; vV = 0.f; eS = DEADE; }
                ab4[rb ^ 1][8 + j] = make_float4(vU, vV, eS, 0);
            }
            rb ^= 1;
        }
        if (w == 4) { asm volatile("cp.async.wait_group 0;" ::: "memory"); }
        // tail (<=7 single steps, log domain, from ring)
        for (int t = 1 + KS * nI; t <= Tm; t++) {
            __syncthreads();
            if (cw) {
                float4 n1 = ab4[rb][7 + j];
                const float* R = &ring[t & 31][0];
                float eB = R[0], eV = R[c[0]];
                acc += ex2f(eV * LOG2E);
                float xU = toLog(vU, eS), xV = toLog(vV, eS);
                float xVm = toLog(n1.y, n1.z);
                float nU = lse2p(xU, xVm, eB);
                float nV = lse3p(xV, xU, (af[0] > 0.5f) ? xVm : NEG2, eV);
                nU = hasU ? nU : NEG2;
                nV = hasV ? nV : NEG2;
                float mx = fmaxf(nU, nV);
                if (mx > -1e29f) {
                    float eI = floorf(mx);
                    vU = ex2f(nU - eI); vV = ex2f(nV - eI); eS = eI;
                } else { vU = 0.f; vV = 0.f; eS = DEADE; }
                ab4[rb ^ 1][8 + j] = make_float4(vU, vV, eS, 0);
            }
            rb ^= 1;
        }
    } else {
        // ======================= BACKWARD =======================
        int   c[KS + 1];
        float aN[KS];
        if (cw) {
            #pragma unroll
            for (int p = 0; p <= KS; p++) {
                int idx = j + p;
                c[p] = (idx < L) ? targets[bL + idx] : 0;
            }
            #pragma unroll
            for (int p = 0; p < KS; p++) {
                int idx = j + p;
                aN[p] = (idx + 1 < L && c[p + 1] != c[p]) ? 1.f : 0.f;
            }
        }
        const int nI = (nB >= KS) ? ((nB - KS) >> 3) + 1 : 0;  // intervals k = 8i, k+7 <= nB-1

        if (w == 4) {
            #pragma unroll
            for (int i = 0; i < 24; i++) {
                if (i < nB) ISSUE(i & 31, len - 1 - i)
                asm volatile("cp.async.commit_group;" ::: "memory");
            }
            asm volatile("cp.async.wait_group 15;" ::: "memory");
        }
        __syncthreads();
        if (cw) {
            vU = (j == tl)     ? 1.f : 0.f;
            vV = (j == tl - 1) ? 1.f : 0.f;
            eS = (vU > 0.f || vV > 0.f) ? 0.f : DEADE;
            ab4[0][j] = make_float4(vU, vV, eS, 0);
        }

        int rb = 0;
        for (int i = 0; i < nI; i++) {
            __syncthreads();
            const int k = KS * i;
            if (w == 4) {
                #pragma unroll
                for (int q = 0; q < 8; q++) {
                    int kk = 24 + 8 * i + q;
                    if (kk < nB) ISSUE(kk & 31, len - 1 - kk)
                    asm volatile("cp.async.commit_group;" ::: "memory");
                }
                asm volatile("cp.async.wait_group 15;" ::: "memory");
            } else if (cw) {
                float U[KS + 1], V[KS + 1];
                float me = eS;
                float4 nb[KS];
                #pragma unroll
                for (int p = 0; p < KS; p++) {
                    nb[p] = ab4[rb][j + 1 + p];
                    me = fmaxf(me, nb[p].z);
                }
                {
                    float s0 = ex2f(eS - me);
                    U[0] = vU * s0; V[0] = vV * s0;
                }
                #pragma unroll
                for (int p = 0; p < KS; p++) {
                    float s = ex2f(nb[p].z - me);
                    U[p + 1] = nb[p].x * s;
                    V[p + 1] = nb[p].y * s;
                }
                #pragma unroll
                for (int s = 0; s < KS; s++) {
                    const float* R = &ring[(k + s) & 31][0];
                    float pB = ex2f(R[0] * LOG2E);
                    float wv[KS + 1];
                    float pa0 = ex2f(R[c[0]] * LOG2E);
                    acc += pa0;
                    wv[0] = V[0] * pa0;
                    #pragma unroll
                    for (int p = 1; p <= KS; p++) {
                        if (p <= KS - s) wv[p] = V[p] * ex2f(R[c[p]] * LOG2E);
                    }
                    #pragma unroll
                    for (int p = 0; p < KS - s; p++) {
                        float nU = fmaf(U[p], pB, wv[p]);
                        float nV = fmaf(aN[p], wv[p + 1], fmaf(U[p + 1], pB, wv[p]));
                        U[p] = nU; V[p] = nV;
                    }
                }
                float qU = hasU ? U[0] : 0.f;
                float qV = hasV ? V[0] : 0.f;
                float mm = fmaxf(qU, qV);
                if (mm > 0.f) {
                    int ex = (int)(__float_as_uint(mm) >> 23) - 127;
                    float scl = __uint_as_float((unsigned)(127 - ex) << 23);
                    vU = qU * scl; vV = qV * scl; eS = me + (float)ex;
                } else { vU = 0.f; vV = 0.f; eS = DEADE; }
                ab4[rb ^ 1][j] = make_float4(vU, vV, eS, 0);
            }
            rb ^= 1;
        }
        if (w == 4) { asm volatile("cp.async.wait_group 0;" ::: "memory"); }
        for (int k = KS * nI; k <= nB - 1; k++) {   // tail (log domain)
            __syncthreads();
            if (cw) {
                float4 n1 = ab4[rb][j + 1];
                const float* R = &ring[k & 31][0];
                float eB = R[0] * LOG2E, eA = R[c[0]] * LOG2E, eC = R[c[1]] * LOG2E;
                acc += ex2f(eA);
                float xU = toLog(vU, eS), xV = toLog(vV, eS);
                float xU1 = toLog(n1.x, n1.z), xV1 = toLog(n1.y, n1.z);
                float nU = lse2(xU + eB, xV + eA);
                float nV = lse3(xV + eA, xU1 + eB, (aN[0] > 0.5f) ? (xV1 + eC) : NEG2);
                nU = hasU ? nU : NEG2;
                nV = hasV ? nV : NEG2;
                float mx = fmaxf(nU, nV);
                if (mx > -1e29f) {
                    float eI = floorf(mx);
                    vU = ex2f(nU - eI); vV = ex2f(nV - eI); eS = eI;
                } else { vU = 0.f; vV = 0.f; eS = DEADE; }
                ab4[rb ^ 1][j] = make_float4(vU, vV, eS, 0);
            }
            rb ^= 1;
        }
    }

    // ---- publish mid-state (log2) + tps partials ----
    if (cw) {
        g_mid[b][dir][j][0] = toLog(vU, eS);
        g_mid[b][dir][j][1] = toLog(vV, eS);
        g_tps[b][dir][j]    = acc;
    }
    __threadfence();
    __syncthreads();
    if (tid == 0) sflag = atomicAdd(&g_done[b], 1u);
    __syncthreads();

    if (sflag == 1) {                    // second finisher: combine this sample
        float cU = NEG2, cV = NEG2, mj = NEG2;
        if (cw) {
            float a0 = __ldcg(&g_mid[b][0][j][0]), a1 = __ldcg(&g_mid[b][0][j][1]);
            float b0 = __ldcg(&g_mid[b][1][j][0]), b1 = __ldcg(&g_mid[b][1][j][1]);
            cU = a0 + b0;  cV = a1 + b1;
            mj = fmaxf(cU, cV);
            #pragma unroll
            for (int o = 16; o; o >>= 1) mj = fmaxf(mj, __shfl_xor_sync(0xFFFFFFFFu, mj, o));
            if (lane == 0) redm[w] = mj;
        }
        __syncthreads();
        float M = fmaxf(fmaxf(redm[0], redm[1]), fmaxf(redm[2], redm[3]));
        float sj = 0.0f, wgt = 0.0f;
        if (cw) {
            sj = ex2f(cU - M) + ex2f(cV - M);
            if (j < L) {
                float tps = __ldcg(&g_tps[b][0][j]) + __ldcg(&g_tps[b][1][j]);
                float om  = 1.0f - tps * (1.0f / (float)T);
                wgt = om * om;                       // GAMMA = 2
            }
            #pragma unroll
            for (int o = 16; o; o >>= 1) {
                sj  += __shfl_xor_sync(0xFFFFFFFFu, sj, o);
                wgt += __shfl_xor_sync(0xFFFFFFFFu, wgt, o);
            }
            if (lane == 0) { reds[w] = sj; redww[w] = wgt; }
        }
        __syncthreads();
        if (tid == 0) {
            float ss = reds[0] + reds[1] + reds[2] + reds[3];
            float ll = (M + lg2f(ss)) * LN2;
            g_loss[b] = (ll > -5e29f) ? -ll : 0.0f;   // zero_infinity
            g_wsum[b] = redww[0] + redww[1] + redww[2] + redww[3];
            g_done[b] = 0;                            // reset for graph replay
            finalize(out, B, L);
        }
    }
    #undef ISSUE
}

extern "C" void kernel_launch(void* const* d_in, const int* in_sizes, int n_in,
                              void* d_out, int out_size)
{
    const float* lp      = (const float*)d_in[0];
    const int*   targets = (const int*)d_in[1];
    const int*   in_len  = (const int*)d_in[2];
    const int*   tg_len  = (const int*)d_in[3];

    int B = in_sizes[2];                 // 64
    int L = in_sizes[1] / B;             // 100
    int T = in_sizes[0] / (B * CFIX);    // 1000

    focal_ctc_kernel<<<2 * B, 160>>>(lp, targets, in_len, tg_len, (float*)d_out, T, B, L);
}